// round 1
// baseline (speedup 1.0000x reference)
#include <cuda_runtime.h>
#include <math.h>

// ---- problem constants ----
#define BB   4
#define MMOD 4
#define LL   1024
#define DMD  768
#define D2   384
#define LM   4096          // L*M interleaved sequence length
#define DS   8
#define DTR  48
#define NXD  64            // DTR + 2*DS
#define NC   64            // scan chunks
#define CLN  64            // chunk length
#define ROWS (BB*LM)       // 16384 sequence rows

// ---- scratch (static device globals; allocation-free) ----
__device__ float g_xz   [ROWS*DMD];      // interleaved xz, 50 MB
__device__ float g_xc   [ROWS*D2];
__device__ float g_zc   [ROWS*D2];
__device__ float g_xdbl [ROWS*NXD];      // dt(48) | B(8) | C(8)
__device__ float g_delta[ROWS*D2];
__device__ float g_y    [ROWS*D2];
__device__ float g_yg   [ROWS*D2];
__device__ float g_P    [BB*NC*DS*D2];   // [b][c][s][d]
__device__ float g_HL   [BB*NC*DS*D2];
__device__ float g_INIT [BB*NC*DS*D2];

// =====================================================================
// Kernel 1: per-(b,m,l) low-rank in-projection: 768->16, LN, GELU, 16->768
// writes xz modality-interleaved: row = l*M + m
// =====================================================================
__global__ __launch_bounds__(256) void k_inproj(
    const float* __restrict__ hs, const float* __restrict__ w1,
    const float* __restrict__ lng, const float* __restrict__ lnb,
    const float* __restrict__ w2, const int* __restrict__ midx)
{
    int l = blockIdx.x, m = blockIdx.y, b = blockIdx.z;
    int tid = threadIdx.x;
    int wi = midx[m];
    __shared__ float sh[DMD];
    __shared__ float st[16];
    __shared__ float s_mu, s_rstd;

    const float* hrow = hs + ((size_t)(b*MMOD + m)*LL + l)*DMD;
    for (int d = tid; d < DMD; d += 256) sh[d] = hrow[d];
    __syncthreads();

    int w = tid >> 5, lane = tid & 31;
    #pragma unroll
    for (int q = 0; q < 2; q++) {
        int r = w*2 + q;
        const float* wrow = w1 + ((size_t)wi*16 + r)*DMD;
        float s = 0.f;
        for (int d = lane; d < DMD; d += 32) s += sh[d]*wrow[d];
        #pragma unroll
        for (int o = 16; o > 0; o >>= 1) s += __shfl_xor_sync(0xffffffffu, s, o);
        if (lane == 0) st[r] = s;
    }
    __syncthreads();
    if (tid == 0) {
        float mu = 0.f;
        #pragma unroll
        for (int r = 0; r < 16; r++) mu += st[r];
        mu *= (1.f/16.f);
        float var = 0.f;
        #pragma unroll
        for (int r = 0; r < 16; r++) { float d = st[r]-mu; var += d*d; }
        var *= (1.f/16.f);
        s_mu = mu; s_rstd = rsqrtf(var + 1e-5f);
    }
    __syncthreads();
    if (tid < 16) {
        float v = (st[tid]-s_mu)*s_rstd*lng[wi*16+tid] + lnb[wi*16+tid];
        st[tid] = 0.5f*v*(1.f + erff(v*0.70710678118654752f));   // exact GELU
    }
    __syncthreads();

    float tr[16];
    #pragma unroll
    for (int r = 0; r < 16; r++) tr[r] = st[r];
    float* orow = g_xz + ((size_t)b*LM + (l*MMOD + m))*DMD;
    for (int d = tid; d < DMD; d += 256) {
        const float* w2r = w2 + ((size_t)wi*DMD + d)*16;
        float s = 0.f;
        #pragma unroll
        for (int r = 0; r < 16; r++) s += tr[r]*w2r[r];
        orow[d] = s;
    }
}

// =====================================================================
// Kernel 2a: depthwise conv (k=3, SAME, zero pad) + SiLU on x and z halves
// =====================================================================
__global__ void k_conv(const float* __restrict__ wx, const float* __restrict__ wz)
{
    int idx = blockIdx.x*blockDim.x + threadIdx.x;
    if (idx >= ROWS*D2) return;
    int c = idx % D2;
    int row = idx / D2;
    int t = row & (LM-1);
    const float* base = g_xz + (size_t)row*DMD;

    float xm = (t > 0)      ? base[c - DMD] : 0.f;
    float x0 = base[c];
    float xp = (t < LM-1)   ? base[c + DMD] : 0.f;
    float vx = wx[c*3+0]*xm + wx[c*3+1]*x0 + wx[c*3+2]*xp;
    g_xc[idx] = vx / (1.f + __expf(-vx));

    float zm = (t > 0)      ? base[c+D2 - DMD] : 0.f;
    float z0 = base[c+D2];
    float zp = (t < LM-1)   ? base[c+D2 + DMD] : 0.f;
    float vz = wz[c*3+0]*zm + wz[c*3+1]*z0 + wz[c*3+2]*zp;
    g_zc[idx] = vz / (1.f + __expf(-vz));
}

// =====================================================================
// Generic tiled GEMM 64x64x16, 4x4 thread tile. C[r][n] = sum_k A[r][k]*B[n][k]
// EPI=0: plain store;  EPI=1: softplus(acc + 2*bias[n])
// =====================================================================
template<int EPI>
__global__ __launch_bounds__(256) void k_gemm64(
    const float* __restrict__ A, int lda, int K,
    const float* __restrict__ Bw, int ldb,
    float* __restrict__ C, int ldc,
    const float* __restrict__ bias)
{
    __shared__ float As[16][65];
    __shared__ float Bs[16][65];
    int tid = threadIdx.x;
    int row0 = blockIdx.y*64, col0 = blockIdx.x*64;
    int tx = tid & 15, ty = tid >> 4;
    float acc[4][4] = {};

    for (int k0 = 0; k0 < K; k0 += 16) {
        int i  = tid >> 2;
        int kk = (tid & 3)*4;
        float4 av = *(const float4*)(A  + (size_t)(row0+i)*lda + k0 + kk);
        float4 bv = *(const float4*)(Bw + (size_t)(col0+i)*ldb + k0 + kk);
        __syncthreads();
        As[kk+0][i]=av.x; As[kk+1][i]=av.y; As[kk+2][i]=av.z; As[kk+3][i]=av.w;
        Bs[kk+0][i]=bv.x; Bs[kk+1][i]=bv.y; Bs[kk+2][i]=bv.z; Bs[kk+3][i]=bv.w;
        __syncthreads();
        #pragma unroll
        for (int k = 0; k < 16; k++) {
            float a[4], bb[4];
            #pragma unroll
            for (int q = 0; q < 4; q++) { a[q] = As[k][ty*4+q]; bb[q] = Bs[k][tx*4+q]; }
            #pragma unroll
            for (int ii = 0; ii < 4; ii++)
                #pragma unroll
                for (int jj = 0; jj < 4; jj++)
                    acc[ii][jj] += a[ii]*bb[jj];
        }
    }
    #pragma unroll
    for (int ii = 0; ii < 4; ii++) {
        int r = row0 + ty*4 + ii;
        #pragma unroll
        for (int jj = 0; jj < 4; jj++) {
            int cc = col0 + tx*4 + jj;
            float v = acc[ii][jj];
            if (EPI == 1) {
                v += 2.f*bias[cc];
                v = (v > 20.f) ? v : log1pf(expf(v));
            }
            C[(size_t)r*ldc + cc] = v;
        }
    }
}

// =====================================================================
// Kernel 3a: scan phase A — per (b, chunk, d): chunk-local scan from 0,
// emit cumulative dA-product P and local end state HL.
// =====================================================================
__global__ __launch_bounds__(384) void k_scanA(const float* __restrict__ A_log)
{
    int c = blockIdx.x, b = blockIdx.y;
    int d = threadIdx.x;
    __shared__ float sB[CLN][8];
    for (int e = d; e < CLN*8; e += 384) {
        int j = e >> 3, s = e & 7;
        sB[j][s] = g_xdbl[((size_t)(b*LM + c*CLN + j))*NXD + 48 + s];
    }
    __syncthreads();
    float As[8];
    #pragma unroll
    for (int s = 0; s < 8; s++) As[s] = -__expf(A_log[d*8+s]);
    float h[8] = {}, P[8];
    #pragma unroll
    for (int s = 0; s < 8; s++) P[s] = 1.f;
    int rbase = b*LM + c*CLN;
    for (int j = 0; j < CLN; j++) {
        float dl = g_delta[(size_t)(rbase+j)*D2 + d];
        float xv = g_xc  [(size_t)(rbase+j)*D2 + d];
        float dx = dl*xv;
        #pragma unroll
        for (int s = 0; s < 8; s++) {
            float a = __expf(dl*As[s]);
            h[s] = a*h[s] + dx*sB[j][s];
            P[s] *= a;
        }
    }
    size_t o = ((size_t)(b*NC + c)*8)*D2 + d;
    #pragma unroll
    for (int s = 0; s < 8; s++) { g_P[o + (size_t)s*D2] = P[s]; g_HL[o + (size_t)s*D2] = h[s]; }
}

// Kernel 3b: sequential carry across chunks per (b,d,s)
__global__ void k_scanB()
{
    int tid = blockIdx.x*blockDim.x + threadIdx.x;
    if (tid >= BB*D2*8) return;
    int d = tid % D2;
    int s = (tid / D2) & 7;
    int b = tid / (D2*8);
    float carry = 0.f;
    for (int c = 0; c < NC; c++) {
        size_t o = ((size_t)(b*NC + c)*8 + s)*D2 + d;
        g_INIT[o] = carry;
        carry = g_P[o]*carry + g_HL[o];
    }
}

// Kernel 3c: phase C — replay with init state, emit y = h.C + D*x
__global__ __launch_bounds__(384) void k_scanC(const float* __restrict__ A_log,
                                               const float* __restrict__ Dw)
{
    int c = blockIdx.x, b = blockIdx.y;
    int d = threadIdx.x;
    __shared__ float sB[CLN][8];
    __shared__ float sC[CLN][8];
    for (int e = d; e < CLN*8; e += 384) {
        int j = e >> 3, s = e & 7;
        size_t rr = ((size_t)(b*LM + c*CLN + j))*NXD;
        sB[j][s] = g_xdbl[rr + 48 + s];
        sC[j][s] = g_xdbl[rr + 56 + s];
    }
    __syncthreads();
    float As[8];
    #pragma unroll
    for (int s = 0; s < 8; s++) As[s] = -__expf(A_log[d*8+s]);
    float h[8];
    size_t o = ((size_t)(b*NC + c)*8)*D2 + d;
    #pragma unroll
    for (int s = 0; s < 8; s++) h[s] = g_INIT[o + (size_t)s*D2];
    float Dv = Dw[d];
    int rbase = b*LM + c*CLN;
    for (int j = 0; j < CLN; j++) {
        float dl = g_delta[(size_t)(rbase+j)*D2 + d];
        float xv = g_xc  [(size_t)(rbase+j)*D2 + d];
        float dx = dl*xv;
        float y = Dv*xv;
        #pragma unroll
        for (int s = 0; s < 8; s++) {
            float a = __expf(dl*As[s]);
            h[s] = a*h[s] + dx*sB[j][s];
            y += h[s]*sC[j][s];
        }
        g_y[(size_t)(rbase+j)*D2 + d] = y;
    }
}

// =====================================================================
// Kernel 4: RMSNorm over d2 + gate with silu(zc) (zc already SiLU'd once)
// =====================================================================
__global__ __launch_bounds__(128) void k_rmsgate(const float* __restrict__ nw)
{
    int row = blockIdx.x;
    int tid = threadIdx.x;
    const float* yr = g_y  + (size_t)row*D2;
    const float* zr = g_zc + (size_t)row*D2;
    float v[3];
    float ss = 0.f;
    #pragma unroll
    for (int q = 0; q < 3; q++) { v[q] = yr[tid + q*128]; ss += v[q]*v[q]; }
    __shared__ float red[4];
    #pragma unroll
    for (int o = 16; o > 0; o >>= 1) ss += __shfl_xor_sync(0xffffffffu, ss, o);
    if ((tid & 31) == 0) red[tid >> 5] = ss;
    __syncthreads();
    float tot = red[0]+red[1]+red[2]+red[3];
    float rn = rsqrtf(tot*(1.f/384.f) + 1e-5f);
    float* og = g_yg + (size_t)row*D2;
    #pragma unroll
    for (int q = 0; q < 3; q++) {
        int dd = tid + q*128;
        float z = zr[dd];
        float sz = z/(1.f + __expf(-z));
        og[dd] = v[q]*rn*nw[dd]*sz;
    }
}

// =====================================================================
// Kernel 5: out-projection per modality; 128x128x8 tiled, packed f32x2 FMA.
// out[b][m][l][o] = scale * sum_d yg[b, l*M+m, d] * out_w[wi][o][d]
// =====================================================================
__device__ __forceinline__ unsigned long long f32x2_dup(float x) {
    unsigned long long r; unsigned u = __float_as_uint(x);
    asm("mov.b64 %0, {%1, %2};" : "=l"(r) : "r"(u), "r"(u));
    return r;
}
__device__ __forceinline__ void f32x2_fma(unsigned long long& d,
                                          unsigned long long a, unsigned long long b) {
    asm("fma.rn.f32x2 %0, %1, %2, %0;" : "+l"(d) : "l"(a), "l"(b));
}

__global__ __launch_bounds__(256) void k_outproj(
    const float* __restrict__ Wo, const float* __restrict__ scale_p,
    float* __restrict__ out, const int* __restrict__ midx)
{
    int m = blockIdx.z;
    int wi = midx[m];
    __shared__ float As[8][136];
    __shared__ float Bs[8][136];
    int tid = threadIdx.x;
    int tx = tid & 15, ty = tid >> 4;
    int row0 = blockIdx.y*128, col0 = blockIdx.x*128;

    unsigned long long acc[8][4];
    #pragma unroll
    for (int i = 0; i < 8; i++)
        #pragma unroll
        for (int j = 0; j < 4; j++) acc[i][j] = 0ull;

    int ldrow = tid >> 1;
    int ldk   = (tid & 1)*4;
    int arow  = row0 + ldrow;
    int ab = arow >> 10, al = arow & 1023;
    const float* aptr = g_yg + ((size_t)(ab*LM) + al*MMOD + m)*D2 + ldk;
    const float* bptr = Wo + ((size_t)(wi*DMD) + col0 + ldrow)*D2 + ldk;

    for (int k0 = 0; k0 < D2; k0 += 8) {
        float4 av = *(const float4*)(aptr + k0);
        float4 bv = *(const float4*)(bptr + k0);
        __syncthreads();
        As[ldk+0][ldrow]=av.x; As[ldk+1][ldrow]=av.y; As[ldk+2][ldrow]=av.z; As[ldk+3][ldrow]=av.w;
        Bs[ldk+0][ldrow]=bv.x; Bs[ldk+1][ldrow]=bv.y; Bs[ldk+2][ldrow]=bv.z; Bs[ldk+3][ldrow]=bv.w;
        __syncthreads();
        #pragma unroll
        for (int kk = 0; kk < 8; kk++) {
            float4 a0 = *(const float4*)(&As[kk][ty*8]);
            float4 a1 = *(const float4*)(&As[kk][ty*8+4]);
            ulonglong2 b01 = *(const ulonglong2*)(&Bs[kk][tx*8]);
            ulonglong2 b23 = *(const ulonglong2*)(&Bs[kk][tx*8+4]);
            float a[8] = {a0.x,a0.y,a0.z,a0.w,a1.x,a1.y,a1.z,a1.w};
            unsigned long long bp[4] = {b01.x, b01.y, b23.x, b23.y};
            #pragma unroll
            for (int i = 0; i < 8; i++) {
                unsigned long long ad = f32x2_dup(a[i]);
                #pragma unroll
                for (int j = 0; j < 4; j++) f32x2_fma(acc[i][j], ad, bp[j]);
            }
        }
    }

    float s = *scale_p;
    #pragma unroll
    for (int i = 0; i < 8; i++) {
        int r = row0 + ty*8 + i;
        int ob = r >> 10, ol = r & 1023;
        float* orow = out + ((size_t)(ob*MMOD + m)*LL + ol)*DMD + col0 + tx*8;
        float vals[8];
        #pragma unroll
        for (int j = 0; j < 4; j++) {
            unsigned long long v = acc[i][j];
            vals[2*j+0] = __uint_as_float((unsigned)(v & 0xffffffffull)) * s;
            vals[2*j+1] = __uint_as_float((unsigned)(v >> 32)) * s;
        }
        *(float4*)(orow)     = make_float4(vals[0],vals[1],vals[2],vals[3]);
        *(float4*)(orow + 4) = make_float4(vals[4],vals[5],vals[6],vals[7]);
    }
}

// =====================================================================
extern "C" void kernel_launch(void* const* d_in, const int* in_sizes, int n_in,
                              void* d_out, int out_size)
{
    const float* hs   = (const float*)d_in[0];
    const float* w1   = (const float*)d_in[1];
    const float* lng  = (const float*)d_in[2];
    const float* lnb  = (const float*)d_in[3];
    const float* w2   = (const float*)d_in[4];
    const float* xpw  = (const float*)d_in[5];
    const float* dtw  = (const float*)d_in[6];
    const float* dtb  = (const float*)d_in[7];
    const float* alog = (const float*)d_in[8];
    const float* Dp   = (const float*)d_in[9];
    const float* cwx  = (const float*)d_in[10];
    const float* cwz  = (const float*)d_in[11];
    const float* nw   = (const float*)d_in[12];
    const float* outw = (const float*)d_in[13];
    const float* scl  = (const float*)d_in[14];
    const int*   midx = (const int*)d_in[15];
    float* out = (float*)d_out;

    float *p_xc, *p_xdbl, *p_delta;
    cudaGetSymbolAddress((void**)&p_xc,    g_xc);
    cudaGetSymbolAddress((void**)&p_xdbl,  g_xdbl);
    cudaGetSymbolAddress((void**)&p_delta, g_delta);

    k_inproj<<<dim3(LL, MMOD, BB), 256>>>(hs, w1, lng, lnb, w2, midx);
    k_conv<<<(ROWS*D2 + 255)/256, 256>>>(cwx, cwz);
    k_gemm64<0><<<dim3(1, ROWS/64), 256>>>(p_xc, D2, D2, xpw, D2, p_xdbl, NXD, nullptr);
    k_gemm64<1><<<dim3(D2/64, ROWS/64), 256>>>(p_xdbl, NXD, DTR, dtw, DTR, p_delta, D2, dtb);
    k_scanA<<<dim3(NC, BB), 384>>>(alog);
    k_scanB<<<(BB*D2*8 + 255)/256, 256>>>();
    k_scanC<<<dim3(NC, BB), 384>>>(alog, Dp);
    k_rmsgate<<<ROWS, 128>>>(nw);
    k_outproj<<<dim3(DMD/128, (BB*LL)/128, MMOD), 256>>>(outw, scl, out, midx);
}

// round 4
// speedup vs baseline: 1.9122x; 1.9122x over previous
#include <cuda_runtime.h>
#include <cuda_bf16.h>
#include <math.h>
#include <stdint.h>

// ---- problem constants ----
#define BB   4
#define MMOD 4
#define LL   1024
#define DMD  768
#define D2   384
#define LM   4096
#define DS   8
#define DTR  48
#define NXD  64
#define NC   64
#define CLN  64
#define ROWS (BB*LM)

// ---- scratch ----
__device__ float g_xz   [ROWS*DMD];
__device__ float g_xc   [ROWS*D2];
__device__ float g_zc   [ROWS*D2];
__device__ float g_xdbl [ROWS*NXD];
__device__ float g_delta[ROWS*D2];
__device__ float g_y    [ROWS*D2];
__device__ float g_yg   [ROWS*D2];          // tf32-rounded gated output
__device__ float g_Wtf  [MMOD*DMD*D2];      // tf32-rounded out weights, [m][o][d]
__device__ float g_P    [BB*NC*DS*D2];
__device__ float g_HL   [BB*NC*DS*D2];
__device__ float g_INIT [BB*NC*DS*D2];

// =====================================================================
// Kernel 1: low-rank in-projection (float4-vectorized)
// =====================================================================
__global__ __launch_bounds__(256) void k_inproj(
    const float* __restrict__ hs, const float* __restrict__ w1,
    const float* __restrict__ lng, const float* __restrict__ lnb,
    const float* __restrict__ w2, const int* __restrict__ midx)
{
    int l = blockIdx.x, m = blockIdx.y, b = blockIdx.z;
    int tid = threadIdx.x;
    int wi = midx[m];
    __shared__ float sh[DMD];
    __shared__ float st[16];
    __shared__ float s_mu, s_rstd;

    const float* hrow = hs + ((size_t)(b*MMOD + m)*LL + l)*DMD;
    for (int d = tid; d < DMD/4; d += 256)
        ((float4*)sh)[d] = ((const float4*)hrow)[d];
    __syncthreads();

    int w = tid >> 5, lane = tid & 31;
    #pragma unroll
    for (int q = 0; q < 2; q++) {
        int r = w*2 + q;
        const float* wrow = w1 + ((size_t)wi*16 + r)*DMD;
        float s = 0.f;
        #pragma unroll
        for (int d0 = lane*4; d0 < DMD; d0 += 128) {
            float4 h4 = *(const float4*)(sh + d0);
            float4 w4 = *(const float4*)(wrow + d0);
            s += h4.x*w4.x + h4.y*w4.y + h4.z*w4.z + h4.w*w4.w;
        }
        #pragma unroll
        for (int o = 16; o > 0; o >>= 1) s += __shfl_xor_sync(0xffffffffu, s, o);
        if (lane == 0) st[r] = s;
    }
    __syncthreads();
    if (tid == 0) {
        float mu = 0.f;
        #pragma unroll
        for (int r = 0; r < 16; r++) mu += st[r];
        mu *= (1.f/16.f);
        float var = 0.f;
        #pragma unroll
        for (int r = 0; r < 16; r++) { float d = st[r]-mu; var += d*d; }
        var *= (1.f/16.f);
        s_mu = mu; s_rstd = rsqrtf(var + 1e-5f);
    }
    __syncthreads();
    if (tid < 16) {
        float v = (st[tid]-s_mu)*s_rstd*lng[wi*16+tid] + lnb[wi*16+tid];
        st[tid] = 0.5f*v*(1.f + erff(v*0.70710678118654752f));
    }
    __syncthreads();

    float tr[16];
    #pragma unroll
    for (int r = 0; r < 16; r++) tr[r] = st[r];
    float* orow = g_xz + ((size_t)b*LM + (l*MMOD + m))*DMD;
    for (int d = tid; d < DMD; d += 256) {
        const float4* w2r = (const float4*)(w2 + ((size_t)wi*DMD + d)*16);
        float s = 0.f;
        #pragma unroll
        for (int q = 0; q < 4; q++) {
            float4 wv = w2r[q];
            s += tr[q*4+0]*wv.x + tr[q*4+1]*wv.y + tr[q*4+2]*wv.z + tr[q*4+3]*wv.w;
        }
        orow[d] = s;
    }
}

// =====================================================================
// Kernel 2: depthwise conv k=3 + SiLU on both halves
// =====================================================================
__global__ void k_conv(const float* __restrict__ wx, const float* __restrict__ wz)
{
    int idx = blockIdx.x*blockDim.x + threadIdx.x;
    if (idx >= ROWS*D2) return;
    int c = idx % D2;
    int row = idx / D2;
    int t = row & (LM-1);
    const float* base = g_xz + (size_t)row*DMD;

    float xm = (t > 0)      ? base[c - DMD] : 0.f;
    float x0 = base[c];
    float xp = (t < LM-1)   ? base[c + DMD] : 0.f;
    float vx = wx[c*3+0]*xm + wx[c*3+1]*x0 + wx[c*3+2]*xp;
    g_xc[idx] = vx / (1.f + __expf(-vx));

    float zm = (t > 0)      ? base[c+D2 - DMD] : 0.f;
    float z0 = base[c+D2];
    float zp = (t < LM-1)   ? base[c+D2 + DMD] : 0.f;
    float vz = wz[c*3+0]*zm + wz[c*3+1]*z0 + wz[c*3+2]*zp;
    g_zc[idx] = vz / (1.f + __expf(-vz));
}

// =====================================================================
// Tiled 64x64x16 GEMM (x_proj / dt_proj)
// =====================================================================
template<int EPI>
__global__ __launch_bounds__(256) void k_gemm64(
    const float* __restrict__ A, int lda, int K,
    const float* __restrict__ Bw, int ldb,
    float* __restrict__ C, int ldc,
    const float* __restrict__ bias)
{
    __shared__ float As[16][65];
    __shared__ float Bs[16][65];
    int tid = threadIdx.x;
    int row0 = blockIdx.y*64, col0 = blockIdx.x*64;
    int tx = tid & 15, ty = tid >> 4;
    float acc[4][4] = {};

    for (int k0 = 0; k0 < K; k0 += 16) {
        int i  = tid >> 2;
        int kk = (tid & 3)*4;
        float4 av = *(const float4*)(A  + (size_t)(row0+i)*lda + k0 + kk);
        float4 bv = *(const float4*)(Bw + (size_t)(col0+i)*ldb + k0 + kk);
        __syncthreads();
        As[kk+0][i]=av.x; As[kk+1][i]=av.y; As[kk+2][i]=av.z; As[kk+3][i]=av.w;
        Bs[kk+0][i]=bv.x; Bs[kk+1][i]=bv.y; Bs[kk+2][i]=bv.z; Bs[kk+3][i]=bv.w;
        __syncthreads();
        #pragma unroll
        for (int k = 0; k < 16; k++) {
            float a[4], bb[4];
            #pragma unroll
            for (int q = 0; q < 4; q++) { a[q] = As[k][ty*4+q]; bb[q] = Bs[k][tx*4+q]; }
            #pragma unroll
            for (int ii = 0; ii < 4; ii++)
                #pragma unroll
                for (int jj = 0; jj < 4; jj++)
                    acc[ii][jj] += a[ii]*bb[jj];
        }
    }
    #pragma unroll
    for (int ii = 0; ii < 4; ii++) {
        int r = row0 + ty*4 + ii;
        #pragma unroll
        for (int jj = 0; jj < 4; jj++) {
            int cc = col0 + tx*4 + jj;
            float v = acc[ii][jj];
            if (EPI == 1) {
                v += 2.f*bias[cc];
                v = (v > 20.f) ? v : log1pf(expf(v));
            }
            C[(size_t)r*ldc + cc] = v;
        }
    }
}

// =====================================================================
// Scan phase A / B / C
// =====================================================================
__global__ __launch_bounds__(384) void k_scanA(const float* __restrict__ A_log)
{
    int c = blockIdx.x, b = blockIdx.y;
    int d = threadIdx.x;
    __shared__ float sB[CLN][8];
    for (int e = d; e < CLN*8; e += 384) {
        int j = e >> 3, s = e & 7;
        sB[j][s] = g_xdbl[((size_t)(b*LM + c*CLN + j))*NXD + 48 + s];
    }
    __syncthreads();
    float As[8];
    #pragma unroll
    for (int s = 0; s < 8; s++) As[s] = -__expf(A_log[d*8+s]);
    float h[8] = {}, P[8];
    #pragma unroll
    for (int s = 0; s < 8; s++) P[s] = 1.f;
    int rbase = b*LM + c*CLN;
    for (int j = 0; j < CLN; j++) {
        float dl = g_delta[(size_t)(rbase+j)*D2 + d];
        float xv = g_xc  [(size_t)(rbase+j)*D2 + d];
        float dx = dl*xv;
        #pragma unroll
        for (int s = 0; s < 8; s++) {
            float a = __expf(dl*As[s]);
            h[s] = a*h[s] + dx*sB[j][s];
            P[s] *= a;
        }
    }
    size_t o = ((size_t)(b*NC + c)*8)*D2 + d;
    #pragma unroll
    for (int s = 0; s < 8; s++) { g_P[o + (size_t)s*D2] = P[s]; g_HL[o + (size_t)s*D2] = h[s]; }
}

__global__ void k_scanB()
{
    int tid = blockIdx.x*blockDim.x + threadIdx.x;
    if (tid >= BB*D2*8) return;
    int d = tid % D2;
    int s = (tid / D2) & 7;
    int b = tid / (D2*8);
    float carry = 0.f;
    for (int c = 0; c < NC; c++) {
        size_t o = ((size_t)(b*NC + c)*8 + s)*D2 + d;
        g_INIT[o] = carry;
        carry = g_P[o]*carry + g_HL[o];
    }
}

__global__ __launch_bounds__(384) void k_scanC(const float* __restrict__ A_log,
                                               const float* __restrict__ Dw)
{
    int c = blockIdx.x, b = blockIdx.y;
    int d = threadIdx.x;
    __shared__ float sB[CLN][8];
    __shared__ float sC[CLN][8];
    for (int e = d; e < CLN*8; e += 384) {
        int j = e >> 3, s = e & 7;
        size_t rr = ((size_t)(b*LM + c*CLN + j))*NXD;
        sB[j][s] = g_xdbl[rr + 48 + s];
        sC[j][s] = g_xdbl[rr + 56 + s];
    }
    __syncthreads();
    float As[8];
    #pragma unroll
    for (int s = 0; s < 8; s++) As[s] = -__expf(A_log[d*8+s]);
    float h[8];
    size_t o = ((size_t)(b*NC + c)*8)*D2 + d;
    #pragma unroll
    for (int s = 0; s < 8; s++) h[s] = g_INIT[o + (size_t)s*D2];
    float Dv = Dw[d];
    int rbase = b*LM + c*CLN;
    for (int j = 0; j < CLN; j++) {
        float dl = g_delta[(size_t)(rbase+j)*D2 + d];
        float xv = g_xc  [(size_t)(rbase+j)*D2 + d];
        float dx = dl*xv;
        float y = Dv*xv;
        #pragma unroll
        for (int s = 0; s < 8; s++) {
            float a = __expf(dl*As[s]);
            h[s] = a*h[s] + dx*sB[j][s];
            y += h[s]*sC[j][s];
        }
        g_y[(size_t)(rbase+j)*D2 + d] = y;
    }
}

// =====================================================================
// Kernel 4: RMSNorm + gate; writes tf32-rounded fp32
// =====================================================================
__global__ __launch_bounds__(128) void k_rmsgate(const float* __restrict__ nw)
{
    int row = blockIdx.x;
    int tid = threadIdx.x;
    const float* yr = g_y  + (size_t)row*D2;
    const float* zr = g_zc + (size_t)row*D2;
    float v[3];
    float ss = 0.f;
    #pragma unroll
    for (int q = 0; q < 3; q++) { v[q] = yr[tid + q*128]; ss += v[q]*v[q]; }
    __shared__ float red[4];
    #pragma unroll
    for (int o = 16; o > 0; o >>= 1) ss += __shfl_xor_sync(0xffffffffu, ss, o);
    if ((tid & 31) == 0) red[tid >> 5] = ss;
    __syncthreads();
    float tot = red[0]+red[1]+red[2]+red[3];
    float rn = rsqrtf(tot*(1.f/384.f) + 1e-5f);
    float* og = g_yg + (size_t)row*D2;
    #pragma unroll
    for (int q = 0; q < 3; q++) {
        int dd = tid + q*128;
        float z = zr[dd];
        float sz = z/(1.f + __expf(-z));
        float val = v[q]*rn*nw[dd]*sz;
        uint32_t u;
        asm("cvt.rna.tf32.f32 %0, %1;" : "=r"(u) : "f"(val));
        og[dd] = __uint_as_float(u);
    }
}

// =====================================================================
// Kernel 4b: tf32-round out weights into [m][o][d]
// =====================================================================
__global__ __launch_bounds__(384) void k_prepW(const float* __restrict__ outw,
                                               const int* __restrict__ midx)
{
    int o = blockIdx.x, m = blockIdx.y;
    int d = threadIdx.x;
    int wi = midx[m];
    float w = outw[((size_t)wi*DMD + o)*D2 + d];
    uint32_t u;
    asm("cvt.rna.tf32.f32 %0, %1;" : "=r"(u) : "f"(w));
    g_Wtf[(size_t)(m*DMD + o)*D2 + d] = __uint_as_float(u);
}

// =====================================================================
// Kernel 5: out-projection via mma.sync tf32. Per modality m:
//   C[4096,768] = A[4096,384] * W[768,384]^T   (A interleave-indexed)
// BM=128, BN=128, BK=16, 256 thr (8 warps: 2m x 4n), warp tile 64x32.
// grid = (DMD/128, (BB*LL)/128, MMOD)   <-- grid.y = 32, NOT ROWS/128
// =====================================================================
#define BKP 20           // BK + 4 pad (conflict-free fragment reads)
#define NKIT 24          // 384/16

__device__ __forceinline__ void cpa16(uint32_t dst, const void* src) {
    asm volatile("cp.async.cg.shared.global [%0], [%1], 16;" :: "r"(dst), "l"(src));
}
#define MMA_TF32(c, a, b) \
    asm volatile("mma.sync.aligned.m16n8k8.row.col.f32.tf32.tf32.f32 " \
        "{%0,%1,%2,%3}, {%4,%5,%6,%7}, {%8,%9}, {%0,%1,%2,%3};" \
        : "+f"((c)[0]), "+f"((c)[1]), "+f"((c)[2]), "+f"((c)[3]) \
        : "r"(__float_as_uint((a)[0])), "r"(__float_as_uint((a)[1])), \
          "r"(__float_as_uint((a)[2])), "r"(__float_as_uint((a)[3])), \
          "r"(__float_as_uint((b)[0])), "r"(__float_as_uint((b)[1])))

__global__ __launch_bounds__(256, 2) void k_outproj_mma(
    const float* __restrict__ scale_p, float* __restrict__ out)
{
    __shared__ float As[2][128*BKP];
    __shared__ float Bs[2][128*BKP];

    int tid = threadIdx.x, lane = tid & 31, wid = tid >> 5;
    int m  = blockIdx.z;
    int bx = blockIdx.x, by = blockIdx.y;
    int warp_m = wid & 1;        // 0..1
    int warp_n = wid >> 1;       // 0..3

    // ---- load addressing: each thread 2x16B for A and for B per tile ----
    int lrow = tid >> 1;               // 0..127
    int lk0  = (tid & 1) * 8;          // 0 or 8 (floats)
    int gr = by*128 + lrow;            // 0..4095 (b*L + l)
    int bI = gr >> 10, lI = gr & 1023;
    const float* aptr = g_yg  + ((size_t)(bI*LM + lI*4 + m))*D2 + lk0;
    const float* bptr = g_Wtf + ((size_t)(m*DMD) + bx*128 + lrow)*D2 + lk0;
    uint32_t sAd = (uint32_t)__cvta_generic_to_shared(&As[0][0]) + (lrow*BKP + lk0)*4;
    uint32_t sBd = (uint32_t)__cvta_generic_to_shared(&Bs[0][0]) + (lrow*BKP + lk0)*4;
    const uint32_t BUFB = 128*BKP*4;

    float acc[4][4][4];
    #pragma unroll
    for (int i = 0; i < 4; i++)
        #pragma unroll
        for (int j = 0; j < 4; j++)
            #pragma unroll
            for (int q = 0; q < 4; q++) acc[i][j][q] = 0.f;

    // prologue: tile 0 -> buf 0
    cpa16(sAd,      aptr);
    cpa16(sAd + 16, aptr + 4);
    cpa16(sBd,      bptr);
    cpa16(sBd + 16, bptr + 4);
    asm volatile("cp.async.commit_group;");

    for (int kt = 0; kt < NKIT; kt++) {
        asm volatile("cp.async.wait_group 0;");
        __syncthreads();
        if (kt + 1 < NKIT) {
            uint32_t bo = ((kt+1) & 1) * BUFB;
            const float* ap = aptr + (kt+1)*16;
            const float* bp = bptr + (kt+1)*16;
            cpa16(sAd + bo,      ap);
            cpa16(sAd + bo + 16, ap + 4);
            cpa16(sBd + bo,      bp);
            cpa16(sBd + bo + 16, bp + 4);
            asm volatile("cp.async.commit_group;");
        }
        const float* a_s = &As[kt & 1][0];
        const float* b_s = &Bs[kt & 1][0];
        #pragma unroll
        for (int s = 0; s < 2; s++) {
            int acol = s*8 + (lane & 3);
            float ar[4][4];
            #pragma unroll
            for (int am = 0; am < 4; am++) {
                int r0 = warp_m*64 + am*16 + (lane >> 2);
                ar[am][0] = a_s[r0*BKP + acol];
                ar[am][1] = a_s[(r0+8)*BKP + acol];
                ar[am][2] = a_s[r0*BKP + acol + 4];
                ar[am][3] = a_s[(r0+8)*BKP + acol + 4];
            }
            float br[4][2];
            #pragma unroll
            for (int an = 0; an < 4; an++) {
                int c0 = warp_n*32 + an*8 + (lane >> 2);
                br[an][0] = b_s[c0*BKP + acol];
                br[an][1] = b_s[c0*BKP + acol + 4];
            }
            #pragma unroll
            for (int am = 0; am < 4; am++)
                #pragma unroll
                for (int an = 0; an < 4; an++)
                    MMA_TF32(acc[am][an], ar[am], br[an]);
        }
    }

    // ---- epilogue ----
    float sc = *scale_p;
    int r_base = by*128 + warp_m*64;
    int c_base = bx*128 + warp_n*32;
    #pragma unroll
    for (int am = 0; am < 4; am++) {
        #pragma unroll
        for (int half = 0; half < 2; half++) {
            int row = r_base + am*16 + (lane >> 2) + half*8;   // 0..4095
            int ob = row >> 10, ol = row & 1023;
            float* orow = out + ((size_t)((ob*MMOD + m)*LL + ol))*DMD;
            #pragma unroll
            for (int an = 0; an < 4; an++) {
                int cc = c_base + an*8 + (lane & 3)*2;
                float2 v;
                v.x = acc[am][an][half*2 + 0] * sc;
                v.y = acc[am][an][half*2 + 1] * sc;
                *(float2*)(orow + cc) = v;
            }
        }
    }
}

// =====================================================================
extern "C" void kernel_launch(void* const* d_in, const int* in_sizes, int n_in,
                              void* d_out, int out_size)
{
    const float* hs   = (const float*)d_in[0];
    const float* w1   = (const float*)d_in[1];
    const float* lng  = (const float*)d_in[2];
    const float* lnb  = (const float*)d_in[3];
    const float* w2   = (const float*)d_in[4];
    const float* xpw  = (const float*)d_in[5];
    const float* dtw  = (const float*)d_in[6];
    const float* dtb  = (const float*)d_in[7];
    const float* alog = (const float*)d_in[8];
    const float* Dp   = (const float*)d_in[9];
    const float* cwx  = (const float*)d_in[10];
    const float* cwz  = (const float*)d_in[11];
    const float* nw   = (const float*)d_in[12];
    const float* outw = (const float*)d_in[13];
    const float* scl  = (const float*)d_in[14];
    const int*   midx = (const int*)d_in[15];
    float* out = (float*)d_out;

    float *p_xc, *p_xdbl, *p_delta;
    cudaGetSymbolAddress((void**)&p_xc,    g_xc);
    cudaGetSymbolAddress((void**)&p_xdbl,  g_xdbl);
    cudaGetSymbolAddress((void**)&p_delta, g_delta);

    k_inproj<<<dim3(LL, MMOD, BB), 256>>>(hs, w1, lng, lnb, w2, midx);
    k_conv<<<(ROWS*D2 + 255)/256, 256>>>(cwx, cwz);
    k_prepW<<<dim3(DMD, MMOD), 384>>>(outw, midx);
    k_gemm64<0><<<dim3(1, ROWS/64), 256>>>(p_xc, D2, D2, xpw, D2, p_xdbl, NXD, nullptr);
    k_gemm64<1><<<dim3(D2/64, ROWS/64), 256>>>(p_xdbl, NXD, DTR, dtw, DTR, p_delta, D2, dtb);
    k_scanA<<<dim3(NC, BB), 384>>>(alog);
    k_scanB<<<(BB*D2*8 + 255)/256, 256>>>();
    k_scanC<<<dim3(NC, BB), 384>>>(alog, Dp);
    k_rmsgate<<<ROWS, 128>>>(nw);
    k_outproj_mma<<<dim3(DMD/128, (BB*LL)/128, MMOD), 256>>>(scl, out);
}